// round 1
// baseline (speedup 1.0000x reference)
#include <cuda_runtime.h>
#include <cuda_bf16.h>
#include <cstdint>

// Problem constants (fixed by the dataset)
#define NUM_E 8
#define TT 16384
#define DD 2048
#define HH 1024

// Tiling
#define BM 128
#define BN 128
#define BK 32
#define BKP 36   // padded smem stride (36 floats = 144B: 16B aligned, conflict-free)

// Scratch (allocation-free rule: __device__ globals)
__device__ float g_t1[(size_t)TT * HH];   // x @ w1^T (gate pre-activation)
__device__ float g_h [(size_t)TT * HH];   // silu(t1) * (x @ w3^T)

__device__ __forceinline__ uint32_t f2tf32(float x) {
    uint32_t r;
    asm("cvt.rna.tf32.f32 %0, %1;" : "=r"(r) : "f"(x));
    return r;
}

__device__ __forceinline__ void mma_tf32(float c[4], const uint32_t a[4],
                                         uint32_t b0, uint32_t b1) {
    asm volatile(
        "mma.sync.aligned.m16n8k8.row.col.f32.tf32.tf32.f32 "
        "{%0,%1,%2,%3}, {%4,%5,%6,%7}, {%8,%9}, {%0,%1,%2,%3};\n"
        : "+f"(c[0]), "+f"(c[1]), "+f"(c[2]), "+f"(c[3])
        : "r"(a[0]), "r"(a[1]), "r"(a[2]), "r"(a[3]), "r"(b0), "r"(b1));
}

// MODE 0: out = g_t1 = A @ W^T                      (A = x, W = w1)
// MODE 1: out = g_h  = silu(g_t1) * (A @ W^T)       (A = x, W = w3)
// MODE 2: out = Dout = g_h @ W^T                    (W = w2)
// A is [*, K] row-major, W is [E, N, K] row-major (so this is A @ W[e]^T).
template<int MODE>
__global__ __launch_bounds__(256, 1)
void moe_gemm(const float* __restrict__ Ain,
              const float* __restrict__ W,
              const int*   __restrict__ counts,
              float*       __restrict__ Dout,
              int N, int K)
{
    extern __shared__ float smem[];
    float* sA = smem;                  // 2 * BM * BKP floats
    float* sB = smem + 2 * BM * BKP;   // 2 * BN * BKP floats

    const float* A  = (MODE == 2) ? g_h : Ain;
    float*      out = (MODE == 0) ? g_t1 : (MODE == 1 ? g_h : Dout);

    const int tid  = threadIdx.x;
    const int lane = tid & 31;
    const int warp = tid >> 5;
    const int wm   = warp & 3;    // 4 warps along M
    const int wn   = warp >> 2;   // 2 warps along N

    const int m0 = blockIdx.y * BM;
    const int n0 = blockIdx.x * BN;

    // Expert lookup: scan cumsum of counts (BM divides every group size here)
    int e = 0, gbase = 0;
    while (e < NUM_E - 1) {
        int c = counts[e];
        if (m0 < gbase + c) break;
        gbase += c; e++;
    }
    const float* Wp = W + (size_t)e * N * K;

    // gmem->reg staging: thread loads rows (tid/8)+32*i, float4 at col (tid%8)*4
    const int lr = tid >> 3;
    const int lc = (tid & 7) * 4;
    const float* Aptr = A  + (size_t)(m0 + lr) * K + lc;
    const float* Bptr = Wp + (size_t)(n0 + lr) * K + lc;

    const int NK = K / BK;

    float4 ra[4], rb[4];
#pragma unroll
    for (int i = 0; i < 4; i++) {
        ra[i] = *(const float4*)(Aptr + (size_t)(32 * i) * K);
        rb[i] = *(const float4*)(Bptr + (size_t)(32 * i) * K);
    }

    float acc[2][8][4];
#pragma unroll
    for (int mt = 0; mt < 2; mt++)
#pragma unroll
        for (int nt = 0; nt < 8; nt++)
#pragma unroll
            for (int i = 0; i < 4; i++) acc[mt][nt][i] = 0.f;

    // Store tile 0 into buffer 0 (round-to-nearest TF32 applied once, here)
#pragma unroll
    for (int i = 0; i < 4; i++) {
        uint4 va = make_uint4(f2tf32(ra[i].x), f2tf32(ra[i].y),
                              f2tf32(ra[i].z), f2tf32(ra[i].w));
        *(uint4*)&sA[(lr + 32 * i) * BKP + lc] = va;
        uint4 vb = make_uint4(f2tf32(rb[i].x), f2tf32(rb[i].y),
                              f2tf32(rb[i].z), f2tf32(rb[i].w));
        *(uint4*)&sB[(lr + 32 * i) * BKP + lc] = vb;
    }
    __syncthreads();

    for (int kt = 0; kt < NK; kt++) {
        const int  cur  = kt & 1;
        const bool more = (kt + 1 < NK);
        if (more) {
            const float* Ap = Aptr + (size_t)(kt + 1) * BK;
            const float* Bp = Bptr + (size_t)(kt + 1) * BK;
#pragma unroll
            for (int i = 0; i < 4; i++) {
                ra[i] = *(const float4*)(Ap + (size_t)(32 * i) * K);
                rb[i] = *(const float4*)(Bp + (size_t)(32 * i) * K);
            }
        }
        const uint32_t* cA = (const uint32_t*)(sA + cur * BM * BKP);
        const uint32_t* cB = (const uint32_t*)(sB + cur * BN * BKP);
#pragma unroll
        for (int ks = 0; ks < 4; ks++) {
            const int kk = ks * 8 + (lane & 3);
            uint32_t afr[2][4];
#pragma unroll
            for (int mt = 0; mt < 2; mt++) {
                const int r = wm * 32 + mt * 16 + (lane >> 2);
                afr[mt][0] = cA[r * BKP + kk];
                afr[mt][1] = cA[(r + 8) * BKP + kk];
                afr[mt][2] = cA[r * BKP + kk + 4];
                afr[mt][3] = cA[(r + 8) * BKP + kk + 4];
            }
#pragma unroll
            for (int nt = 0; nt < 8; nt++) {
                const int c = wn * 64 + nt * 8 + (lane >> 2);
                uint32_t b0 = cB[c * BKP + kk];
                uint32_t b1 = cB[c * BKP + kk + 4];
                mma_tf32(acc[0][nt], afr[0], b0, b1);
                mma_tf32(acc[1][nt], afr[1], b0, b1);
            }
        }
        if (more) {
            // Buffer (1-cur) was last READ in iter kt-1, which ended in a sync:
            // safe to overwrite now; sync after stores publishes for iter kt+1.
            const int nxt = 1 - cur;
            float* dA = sA + nxt * BM * BKP;
            float* dB = sB + nxt * BN * BKP;
#pragma unroll
            for (int i = 0; i < 4; i++) {
                uint4 va = make_uint4(f2tf32(ra[i].x), f2tf32(ra[i].y),
                                      f2tf32(ra[i].z), f2tf32(ra[i].w));
                *(uint4*)&dA[(lr + 32 * i) * BKP + lc] = va;
                uint4 vb = make_uint4(f2tf32(rb[i].x), f2tf32(rb[i].y),
                                      f2tf32(rb[i].z), f2tf32(rb[i].w));
                *(uint4*)&dB[(lr + 32 * i) * BKP + lc] = vb;
            }
            __syncthreads();
        }
    }

    // Epilogue
#pragma unroll
    for (int mt = 0; mt < 2; mt++) {
        const int rbase = m0 + wm * 32 + mt * 16 + (lane >> 2);
#pragma unroll
        for (int nt = 0; nt < 8; nt++) {
            const int c = n0 + wn * 64 + nt * 8 + (lane & 3) * 2;
#pragma unroll
            for (int h2 = 0; h2 < 2; h2++) {
                const int row = rbase + h2 * 8;
                float v0 = acc[mt][nt][h2 * 2];
                float v1 = acc[mt][nt][h2 * 2 + 1];
                if (MODE == 1) {
                    const float2 t = *(const float2*)&g_t1[(size_t)row * N + c];
                    const float s0 = 1.f / (1.f + expf(-t.x));
                    const float s1 = 1.f / (1.f + expf(-t.y));
                    v0 *= t.x * s0;   // silu(t1) * (x@w3^T)
                    v1 *= t.y * s1;
                }
                *(float2*)&out[(size_t)row * N + c] = make_float2(v0, v1);
            }
        }
    }
}

extern "C" void kernel_launch(void* const* d_in, const int* in_sizes, int n_in,
                              void* d_out, int out_size) {
    const float* x   = (const float*)d_in[0];
    const int*   cnt = (const int*)  d_in[1];
    const float* w1  = (const float*)d_in[2];
    const float* w2  = (const float*)d_in[3];
    const float* w3  = (const float*)d_in[4];
    float* out = (float*)d_out;

    const int smem_bytes = 2 * (BM + BN) * BKP * (int)sizeof(float); // 73728
    cudaFuncSetAttribute(moe_gemm<0>, cudaFuncAttributeMaxDynamicSharedMemorySize, smem_bytes);
    cudaFuncSetAttribute(moe_gemm<1>, cudaFuncAttributeMaxDynamicSharedMemorySize, smem_bytes);
    cudaFuncSetAttribute(moe_gemm<2>, cudaFuncAttributeMaxDynamicSharedMemorySize, smem_bytes);

    dim3 g12(HH / BN, TT / BM);   // (8, 128)
    moe_gemm<0><<<g12, 256, smem_bytes>>>(x, w1, cnt, nullptr, HH, DD);
    moe_gemm<1><<<g12, 256, smem_bytes>>>(x, w3, cnt, nullptr, HH, DD);
    dim3 g3(DD / BN, TT / BM);    // (16, 128)
    moe_gemm<2><<<g3, 256, smem_bytes>>>(nullptr, w2, cnt, out, DD, HH);
}

// round 3
// speedup vs baseline: 1.0440x; 1.0440x over previous
#include <cuda_runtime.h>
#include <cstdint>
#include <cmath>

// ── problem constants ──────────────────────────────────────────────────
#define NUM_E 8
#define TT 16384
#define DD 2048
#define HH 1024

// ── tiling ─────────────────────────────────────────────────────────────
#define BM 128
#define BN 128
#define BK 32
#define BKP 36                 // padded row stride in floats (144 B)
#define ROWB (BKP * 4)         // 144 bytes
#define TILEB (BM * ROWB)      // 18432 bytes per tile per stage
#define NTHREADS 512

// ── scratch (allocation-free rule: __device__ globals) ─────────────────
__device__ float g_x [(size_t)TT * DD];          // tf32-rounded x
__device__ float g_w1[(size_t)NUM_E * HH * DD];  // tf32-rounded w1
__device__ float g_w3[(size_t)NUM_E * HH * DD];  // tf32-rounded w3
__device__ float g_w2[(size_t)NUM_E * DD * HH];  // tf32-rounded w2
__device__ float g_h [(size_t)TT * HH];          // silu(x@w1^T)*(x@w3^T), tf32-rounded

// ── PTX helpers ────────────────────────────────────────────────────────
__device__ __forceinline__ uint32_t smem_u32(const void* p) {
    uint32_t a;
    asm("{ .reg .u64 t; cvta.to.shared.u64 t, %1; cvt.u32.u64 %0, t; }"
        : "=r"(a) : "l"(p));
    return a;
}
__device__ __forceinline__ uint32_t f2tf32(float x) {
    uint32_t r;
    asm("cvt.rna.tf32.f32 %0, %1;" : "=r"(r) : "f"(x));
    return r;
}
__device__ __forceinline__ void cpa16(uint32_t dst, const void* src) {
    asm volatile("cp.async.cg.shared.global [%0], [%1], 16;"
                 :: "r"(dst), "l"(src));
}
__device__ __forceinline__ void cpa_commit() {
    asm volatile("cp.async.commit_group;" ::: "memory");
}
template<int N>
__device__ __forceinline__ void cpa_wait() {
    asm volatile("cp.async.wait_group %0;" :: "n"(N) : "memory");
}
__device__ __forceinline__ void mma_tf32(float c[4], const uint32_t a[4],
                                         uint32_t b0, uint32_t b1) {
    asm volatile(
        "mma.sync.aligned.m16n8k8.row.col.f32.tf32.tf32.f32 "
        "{%0,%1,%2,%3}, {%4,%5,%6,%7}, {%8,%9}, {%0,%1,%2,%3};\n"
        : "+f"(c[0]), "+f"(c[1]), "+f"(c[2]), "+f"(c[3])
        : "r"(a[0]), "r"(a[1]), "r"(a[2]), "r"(a[3]), "r"(b0), "r"(b1));
}

// ── elementwise round-to-nearest tf32 copy ─────────────────────────────
__global__ void __launch_bounds__(256)
round_tf32(const float4* __restrict__ src, float4* __restrict__ dst, int n4) {
    for (int i = blockIdx.x * blockDim.x + threadIdx.x; i < n4;
         i += gridDim.x * blockDim.x) {
        float4 v = src[i];
        v.x = __uint_as_float(f2tf32(v.x));
        v.y = __uint_as_float(f2tf32(v.y));
        v.z = __uint_as_float(f2tf32(v.z));
        v.w = __uint_as_float(f2tf32(v.w));
        dst[i] = v;
    }
}

// ── fused grouped GEMM, legacy mma.sync tf32, cp.async S-stage pipeline ─
// PHASE 1: D1 = x@w1^T, D3 = x@w3^T (dual acc); h = silu(D1)*D3 -> g_h [T,H]
// PHASE 2: out = h@w2^T -> Dout [T,D]
// 16 warps as 4(m) x 4(n); warp tile 32x32 per output matrix.
template<int PHASE, int S>
__global__ void __launch_bounds__(NTHREADS, 1)
moe_mm(const int* __restrict__ counts, float* __restrict__ Dout)
{
    extern __shared__ char smem[];
    const uint32_t sb = smem_u32(smem);
    const int tid  = threadIdx.x;
    const int lane = tid & 31;
    const int wid  = tid >> 5;
    const int wm   = wid & 3;          // 0..3 along M
    const int wn   = wid >> 2;         // 0..3 along N

    constexpr int K   = (PHASE == 1) ? DD : HH;   // reduction dim
    constexpr int NW  = (PHASE == 1) ? HH : DD;   // output cols (weight rows)
    constexpr int NKT = K / BK;
    constexpr int NARR = (PHASE == 1) ? 3 : 2;    // A, B0 [, B1]

    const int m0 = blockIdx.y * BM;
    const int n0 = blockIdx.x * BN;

    // expert lookup (BM divides each group size)
    int e = 0, gb = 0;
    while (e < NUM_E - 1) { int c = counts[e]; if (m0 < gb + c) break; gb += c; e++; }

    const float* A  = ((PHASE == 1) ? g_x : g_h) + (size_t)m0 * K;
    const float* B0 = ((PHASE == 1) ? g_w1 : g_w2) + (size_t)e * NW * K + (size_t)n0 * K;
    const float* B1 = g_w3 + (size_t)e * NW * K + (size_t)n0 * K;   // PHASE 1 only

    const uint32_t sA  = sb;
    const uint32_t sB0 = sb + S * TILEB;
    const uint32_t sB1 = sb + 2 * S * TILEB;

    // per-thread producer coords: 2 x 16B chunks per array per stage
    // idx = tid + i*512 in [0,1024): row = idx/8, chunk-col = idx%8
    const int row0 = tid >> 3, ch0 = (tid & 7) * 4;         // i = 0
    const int row1 = (tid + 512) >> 3, ch1 = ch0;           // i = 1 (same chunk col)

    auto load_stage = [&](int p) {
        const int s = p % S;
        const uint32_t so0 = (uint32_t)(row0 * ROWB + ch0 * 4);
        const uint32_t so1 = (uint32_t)(row1 * ROWB + ch1 * 4);
        const size_t go0 = (size_t)row0 * K + (size_t)p * BK + ch0;
        const size_t go1 = (size_t)row1 * K + (size_t)p * BK + ch1;
        cpa16(sA  + s * TILEB + so0, A  + go0);
        cpa16(sA  + s * TILEB + so1, A  + go1);
        cpa16(sB0 + s * TILEB + so0, B0 + go0);
        cpa16(sB0 + s * TILEB + so1, B0 + go1);
        if (PHASE == 1) {
            cpa16(sB1 + s * TILEB + so0, B1 + go0);
            cpa16(sB1 + s * TILEB + so1, B1 + go1);
        }
    };

    float acc0[2][4][4];
    float acc1[PHASE == 1 ? 2 : 1][4][4];   // second accumulator only in phase 1
#pragma unroll
    for (int mt = 0; mt < 2; mt++)
#pragma unroll
        for (int nt = 0; nt < 4; nt++)
#pragma unroll
            for (int i = 0; i < 4; i++) {
                acc0[mt][nt][i] = 0.f;
                if (PHASE == 1) acc1[mt][nt][i] = 0.f;
            }

    // prologue: stages 0..S-2
#pragma unroll
    for (int p = 0; p < S - 1; p++) { load_stage(p); cpa_commit(); }

    const float* fsm = (const float*)smem;   // float view of shared

    for (int kt = 0; kt < NKT; kt++) {
        cpa_wait<S - 2>();
        __syncthreads();

        const int pn = kt + S - 1;
        if (pn < NKT) load_stage(pn);
        cpa_commit();

        const int s = kt % S;
        const uint32_t* cA  = (const uint32_t*)(fsm) + (s * TILEB) / 4;
        const uint32_t* cB0 = (const uint32_t*)(fsm) + (S * TILEB + s * TILEB) / 4;
        const uint32_t* cB1 = (const uint32_t*)(fsm) + (2 * S * TILEB + s * TILEB) / 4;

#pragma unroll
        for (int ks = 0; ks < 4; ks++) {
            const int kk = ks * 8 + (lane & 3);
            uint32_t afr[2][4];
#pragma unroll
            for (int mt = 0; mt < 2; mt++) {
                const int r = wm * 32 + mt * 16 + (lane >> 2);
                afr[mt][0] = cA[r * BKP + kk];
                afr[mt][1] = cA[(r + 8) * BKP + kk];
                afr[mt][2] = cA[r * BKP + kk + 4];
                afr[mt][3] = cA[(r + 8) * BKP + kk + 4];
            }
#pragma unroll
            for (int nt = 0; nt < 4; nt++) {
                const int c = wn * 32 + nt * 8 + (lane >> 2);
                const uint32_t b00 = cB0[c * BKP + kk];
                const uint32_t b01 = cB0[c * BKP + kk + 4];
                mma_tf32(acc0[0][nt], afr[0], b00, b01);
                mma_tf32(acc0[1][nt], afr[1], b00, b01);
                if (PHASE == 1) {
                    const uint32_t b10 = cB1[c * BKP + kk];
                    const uint32_t b11 = cB1[c * BKP + kk + 4];
                    mma_tf32(acc1[0][nt], afr[0], b10, b11);
                    mma_tf32(acc1[1][nt], afr[1], b10, b11);
                }
            }
        }
        __syncthreads();
    }

    // ── epilogue ───────────────────────────────────────────────────────
#pragma unroll
    for (int mt = 0; mt < 2; mt++) {
        const int rbase = m0 + wm * 32 + mt * 16 + (lane >> 2);
#pragma unroll
        for (int nt = 0; nt < 4; nt++) {
            const int c = n0 + wn * 32 + nt * 8 + (lane & 3) * 2;
#pragma unroll
            for (int h2 = 0; h2 < 2; h2++) {
                const int row = rbase + h2 * 8;
                if (PHASE == 1) {
                    const float d1a = acc0[mt][nt][h2 * 2];
                    const float d1b = acc0[mt][nt][h2 * 2 + 1];
                    const float d3a = acc1[mt][nt][h2 * 2];
                    const float d3b = acc1[mt][nt][h2 * 2 + 1];
                    float2 v;
                    v.x = __uint_as_float(f2tf32(d1a / (1.f + expf(-d1a)) * d3a));
                    v.y = __uint_as_float(f2tf32(d1b / (1.f + expf(-d1b)) * d3b));
                    *(float2*)&g_h[(size_t)row * HH + c] = v;
                } else {
                    float2 v = make_float2(acc0[mt][nt][h2 * 2],
                                           acc0[mt][nt][h2 * 2 + 1]);
                    *(float2*)&Dout[(size_t)row * DD + c] = v;
                }
            }
        }
    }
}

// ── host launch ────────────────────────────────────────────────────────
extern "C" void kernel_launch(void* const* d_in, const int* in_sizes, int n_in,
                              void* d_out, int out_size) {
    const float* x   = (const float*)d_in[0];
    const int*   cnt = (const int*)  d_in[1];
    const float* w1  = (const float*)d_in[2];
    const float* w2  = (const float*)d_in[3];
    const float* w3  = (const float*)d_in[4];
    float* out = (float*)d_out;

    void *px, *pw1, *pw3, *pw2;
    cudaGetSymbolAddress(&px,  g_x);
    cudaGetSymbolAddress(&pw1, g_w1);
    cudaGetSymbolAddress(&pw3, g_w3);
    cudaGetSymbolAddress(&pw2, g_w2);

    constexpr int S1 = 3, S2 = 4;
    const int smem1 = 3 * S1 * TILEB;   // 165888 B
    const int smem2 = 2 * S2 * TILEB;   // 147456 B
    cudaFuncSetAttribute(moe_mm<1, S1>, cudaFuncAttributeMaxDynamicSharedMemorySize, smem1);
    cudaFuncSetAttribute(moe_mm<2, S2>, cudaFuncAttributeMaxDynamicSharedMemorySize, smem2);

    // pre-round all operands to tf32 (rna): HW truncation of rounded values
    // is exact, so GEMM numerics match the verified R1 kernel bit-for-bit.
    round_tf32<<<2048, 256>>>((const float4*)x,  (float4*)px,  TT * DD / 4);
    round_tf32<<<1024, 256>>>((const float4*)w1, (float4*)pw1, NUM_E * HH * DD / 4);
    round_tf32<<<1024, 256>>>((const float4*)w3, (float4*)pw3, NUM_E * HH * DD / 4);
    round_tf32<<<1024, 256>>>((const float4*)w2, (float4*)pw2, NUM_E * DD * HH / 4);

    moe_mm<1, S1><<<dim3(HH / BN, TT / BM), NTHREADS, smem1>>>(cnt, nullptr); // (8,128)
    moe_mm<2, S2><<<dim3(DD / BN, TT / BM), NTHREADS, smem2>>>(cnt, out);     // (16,128)
}

// round 8
// speedup vs baseline: 1.2637x; 1.2105x over previous
#include <cuda_runtime.h>
#include <cstdint>
#include <cmath>

// ── problem constants ──────────────────────────────────────────────────
#define NUM_E 8
#define TT 16384
#define DD 2048
#define HH 1024

// ── tiling ─────────────────────────────────────────────────────────────
#define BM 128
#define BN 128
#define BK 32
#define TILEB (BM * 128)      // 16 KB per tile per stage (128B swizzled rows)
#define NTHREADS 256

// ── scratch (allocation-free rule: __device__ globals) ─────────────────
__device__ float g_w1[(size_t)NUM_E * HH * DD];  // tf32-rounded w1
__device__ float g_w3[(size_t)NUM_E * HH * DD];  // tf32-rounded w3
__device__ float g_w2[(size_t)NUM_E * DD * HH];  // tf32-rounded w2
__device__ float g_h [(size_t)TT * HH];          // silu(x@w1^T)*(x@w3^T), tf32-rounded

// ── PTX helpers ────────────────────────────────────────────────────────
__device__ __forceinline__ uint32_t f2tf32(float x) {
    uint32_t r;
    asm("cvt.rna.tf32.f32 %0, %1;" : "=r"(r) : "f"(x));
    return r;
}
__device__ __forceinline__ uint32_t rr_tf32(uint32_t bits) {   // round fp32 bits
    return f2tf32(__uint_as_float(bits));
}
__device__ __forceinline__ void cpa16(uint32_t dst, const void* src) {
    asm volatile("cp.async.cg.shared.global [%0], [%1], 16;"
                 :: "r"(dst), "l"(src));
}
__device__ __forceinline__ void cpa_commit() {
    asm volatile("cp.async.commit_group;" ::: "memory");
}
template<int N>
__device__ __forceinline__ void cpa_wait() {
    asm volatile("cp.async.wait_group %0;" :: "n"(N) : "memory");
}
__device__ __forceinline__ void mma_tf32(float c[4], const uint32_t a[4],
                                         uint32_t b0, uint32_t b1) {
    asm volatile(
        "mma.sync.aligned.m16n8k8.row.col.f32.tf32.tf32.f32 "
        "{%0,%1,%2,%3}, {%4,%5,%6,%7}, {%8,%9}, {%0,%1,%2,%3};\n"
        : "+f"(c[0]), "+f"(c[1]), "+f"(c[2]), "+f"(c[3])
        : "r"(a[0]), "r"(a[1]), "r"(a[2]), "r"(a[3]), "r"(b0), "r"(b1));
}
__device__ __forceinline__ uint32_t smem_u32(const void* p) {
    uint32_t a;
    asm("{ .reg .u64 t; cvta.to.shared.u64 t, %1; cvt.u32.u64 %0, t; }"
        : "=r"(a) : "l"(p));
    return a;
}
// SW128 swizzled float index within a 128x32-float tile (128B rows):
// byte o = r*128 + c*4;  o ^= (o>>3)&0x70  ==  XOR (r&7) into col bits [2:4]
__device__ __forceinline__ uint32_t swz(int r, int c) {
    return (uint32_t)(r * 32 + (c ^ ((r & 7) << 2)));
}

// ── fused rounding of the three weight tensors (one launch) ────────────
__global__ void __launch_bounds__(256)
round_w3x(const float4* __restrict__ s1, float4* __restrict__ d1,
          const float4* __restrict__ s2, float4* __restrict__ d2,
          const float4* __restrict__ s3, float4* __restrict__ d3, int n4) {
    auto rnd = [](float4 v) {
        v.x = __uint_as_float(f2tf32(v.x));
        v.y = __uint_as_float(f2tf32(v.y));
        v.z = __uint_as_float(f2tf32(v.z));
        v.w = __uint_as_float(f2tf32(v.w));
        return v;
    };
    for (int i = blockIdx.x * blockDim.x + threadIdx.x; i < 3 * n4;
         i += gridDim.x * blockDim.x) {
        if (i < n4)            d1[i]          = rnd(s1[i]);
        else if (i < 2 * n4)   d2[i - n4]     = rnd(s2[i - n4]);
        else                   d3[i - 2 * n4] = rnd(s3[i - 2 * n4]);
    }
}

// ── fused grouped GEMM, mma.sync tf32, single-sync cp.async pipeline ───
// PHASE 1: D1 = x@w1^T, D3 = x@w3^T (dual acc); h = silu(D1)*D3 -> g_h [T,H]
//          (x is tf32-RNA-rounded in-kernel after LDS)
// PHASE 2: out = h@w2^T -> Dout [T,D]
// 8 warps as 2(m) x 4(n); warp tile 64x32 per output matrix.
template<int PHASE, int S>
__global__ void __launch_bounds__(NTHREADS, 1)
moe_mm(const float* __restrict__ Xin, const int* __restrict__ counts,
       float* __restrict__ Dout)
{
    extern __shared__ float fsm[];
    const uint32_t sb = smem_u32(fsm);
    const int tid  = threadIdx.x;
    const int lane = tid & 31;
    const int wid  = tid >> 5;
    const int wm   = wid & 1;          // 2 warps along M (64 rows each)
    const int wn   = wid >> 1;         // 4 warps along N (32 cols each)

    constexpr int K   = (PHASE == 1) ? DD : HH;
    constexpr int NW  = (PHASE == 1) ? HH : DD;
    constexpr int NKT = K / BK;

    const int m0 = blockIdx.y * BM;
    const int n0 = blockIdx.x * BN;

    // expert lookup (BM divides each group size)
    int e = 0, gb = 0;
    while (e < NUM_E - 1) { int c = counts[e]; if (m0 < gb + c) break; gb += c; e++; }

    const float* A  = ((PHASE == 1) ? Xin : g_h) + (size_t)m0 * K;
    const float* B0 = ((PHASE == 1) ? g_w1 : g_w2) + (size_t)e * NW * K + (size_t)n0 * K;
    const float* B1 = g_w3 + (size_t)e * NW * K + (size_t)n0 * K;   // PHASE 1 only

    const uint32_t sA  = sb;
    const uint32_t sB0 = sb + S * TILEB;
    const uint32_t sB1 = sb + 2 * S * TILEB;
    const uint32_t* uA  = (const uint32_t*)fsm;
    const uint32_t* uB0 = uA + (S * TILEB) / 4;
    const uint32_t* uB1 = uA + (2 * S * TILEB) / 4;

    // producer: 4 x 16B chunks per array per stage per thread
    auto load_stage = [&](int p) {
        const int s = p % S;
#pragma unroll
        for (int i = 0; i < 4; i++) {
            const int idx = tid + i * NTHREADS;     // 0..1023
            const int row = idx >> 3, ch = idx & 7;
            uint32_t o  = (uint32_t)(row * 128 + ch * 16);
            uint32_t so = o ^ ((o >> 3) & 0x70);
            const size_t go = (size_t)row * K + (size_t)p * BK + ch * 4;
            cpa16(sA + s * TILEB + so, A + go);
            cpa16(sB0 + s * TILEB + so, B0 + go);
            if (PHASE == 1) cpa16(sB1 + s * TILEB + so, B1 + go);
        }
    };

    float acc0[4][4][4];                      // [mt][nt][reg]
    float acc1[PHASE == 1 ? 4 : 1][4][4];
#pragma unroll
    for (int mt = 0; mt < 4; mt++)
#pragma unroll
        for (int nt = 0; nt < 4; nt++)
#pragma unroll
            for (int i = 0; i < 4; i++) {
                acc0[mt][nt][i] = 0.f;
                if (PHASE == 1) acc1[mt][nt][i] = 0.f;
            }

    uint32_t fa[2][4][4];                     // A frags, double-buffered
    uint32_t fb0[2][4][2];                    // B0 frags, double-buffered
    uint32_t fb1[4][2];                       // B1 frags (phase 1), single

    const int rA = wm * 64 + (lane >> 2);     // A row base (+mt*16, +8)
    const int rB = wn * 32 + (lane >> 2);     // B row base (+nt*8)
    const int kl = lane & 3;

    auto ldA = [&](int buf, const uint32_t* p, int ks) {
        const int kk = ks * 8 + kl;
#pragma unroll
        for (int mt = 0; mt < 4; mt++) {
            const int r = rA + mt * 16;
            uint32_t v0 = p[swz(r, kk)],     v1 = p[swz(r + 8, kk)];
            uint32_t v2 = p[swz(r, kk + 4)], v3 = p[swz(r + 8, kk + 4)];
            if (PHASE == 1) { v0 = rr_tf32(v0); v1 = rr_tf32(v1);
                              v2 = rr_tf32(v2); v3 = rr_tf32(v3); }
            fa[buf][mt][0] = v0; fa[buf][mt][1] = v1;
            fa[buf][mt][2] = v2; fa[buf][mt][3] = v3;
        }
    };
    auto ldB0 = [&](int buf, const uint32_t* p, int ks) {
        const int kk = ks * 8 + kl;
#pragma unroll
        for (int nt = 0; nt < 4; nt++) {
            const int c = rB + nt * 8;
            fb0[buf][nt][0] = p[swz(c, kk)];
            fb0[buf][nt][1] = p[swz(c, kk + 4)];
        }
    };
    auto ldB1 = [&](const uint32_t* p, int ks) {
        const int kk = ks * 8 + kl;
#pragma unroll
        for (int nt = 0; nt < 4; nt++) {
            const int c = rB + nt * 8;
            fb1[nt][0] = p[swz(c, kk)];
            fb1[nt][1] = p[swz(c, kk + 4)];
        }
    };
    auto mma_all = [&](int buf) {
#pragma unroll
        for (int nt = 0; nt < 4; nt++)
#pragma unroll
            for (int mt = 0; mt < 4; mt++) {
                mma_tf32(acc0[mt][nt], fa[buf][mt], fb0[buf][nt][0], fb0[buf][nt][1]);
                if (PHASE == 1)
                    mma_tf32(acc1[mt][nt], fa[buf][mt], fb1[nt][0], fb1[nt][1]);
            }
    };

    // ── prologue: stages 0..S-2 in flight, frags for (stage 0, ks 0) ───
#pragma unroll
    for (int p = 0; p < S - 1; p++) { load_stage(p); cpa_commit(); }
    cpa_wait<S - 2>();
    __syncthreads();
    ldA(0, uA, 0);
    ldB0(0, uB0, 0);

    // ── mainloop: one sync per k-tile ──────────────────────────────────
    for (int kt = 0; kt < NKT; kt++) {
        const int s = kt % S;
        const uint32_t* cA  = uA  + (s * TILEB) / 4;
        const uint32_t* cB0 = uB0 + (s * TILEB) / 4;
        const uint32_t* cB1 = uB1 + (s * TILEB) / 4;
#pragma unroll
        for (int ks = 0; ks < 4; ks++) {
            const int cur = ks & 1, nxt = cur ^ 1;
            if (ks == 0) {
                if (kt + S - 1 < NKT) load_stage(kt + S - 1);
                cpa_commit();
            }
            if (PHASE == 1) ldB1(cB1, ks);
            if (ks < 3) {
                ldA(nxt, cA, ks + 1);
                ldB0(nxt, cB0, ks + 1);
                mma_all(cur);
            } else {
                mma_all(cur);
                if (kt + 1 < NKT) {
                    cpa_wait<S - 2>();
                    __syncthreads();
                    const int sn = (kt + 1) % S;
                    ldA(nxt, uA + (sn * TILEB) / 4, 0);
                    ldB0(nxt, uB0 + (sn * TILEB) / 4, 0);
                }
            }
        }
    }

    // ── epilogue ───────────────────────────────────────────────────────
#pragma unroll
    for (int mt = 0; mt < 4; mt++) {
        const int rbase = m0 + wm * 64 + mt * 16 + (lane >> 2);
#pragma unroll
        for (int nt = 0; nt < 4; nt++) {
            const int c = n0 + wn * 32 + nt * 8 + (lane & 3) * 2;
#pragma unroll
            for (int h2 = 0; h2 < 2; h2++) {
                const int row = rbase + h2 * 8;
                if (PHASE == 1) {
                    const float d1a = acc0[mt][nt][h2 * 2];
                    const float d1b = acc0[mt][nt][h2 * 2 + 1];
                    const float d3a = acc1[mt][nt][h2 * 2];
                    const float d3b = acc1[mt][nt][h2 * 2 + 1];
                    float2 v;
                    v.x = __uint_as_float(f2tf32(d1a / (1.f + expf(-d1a)) * d3a));
                    v.y = __uint_as_float(f2tf32(d1b / (1.f + expf(-d1b)) * d3b));
                    *(float2*)&g_h[(size_t)row * HH + c] = v;
                } else {
                    *(float2*)&Dout[(size_t)row * DD + c] =
                        make_float2(acc0[mt][nt][h2 * 2], acc0[mt][nt][h2 * 2 + 1]);
                }
            }
        }
    }
}

// ── host launch ────────────────────────────────────────────────────────
extern "C" void kernel_launch(void* const* d_in, const int* in_sizes, int n_in,
                              void* d_out, int out_size) {
    const float* x   = (const float*)d_in[0];
    const int*   cnt = (const int*)  d_in[1];
    const float* w1  = (const float*)d_in[2];
    const float* w2  = (const float*)d_in[3];
    const float* w3  = (const float*)d_in[4];
    float* out = (float*)d_out;

    void *pw1, *pw3, *pw2;
    cudaGetSymbolAddress(&pw1, g_w1);
    cudaGetSymbolAddress(&pw3, g_w3);
    cudaGetSymbolAddress(&pw2, g_w2);

    constexpr int S1 = 4, S2 = 6;
    const int smem1 = 3 * S1 * TILEB;   // 196608 B
    const int smem2 = 2 * S2 * TILEB;   // 196608 B
    cudaFuncSetAttribute(moe_mm<1, S1>, cudaFuncAttributeMaxDynamicSharedMemorySize, smem1);
    cudaFuncSetAttribute(moe_mm<2, S2>, cudaFuncAttributeMaxDynamicSharedMemorySize, smem2);

    // round the three weight tensors to tf32 (rna) in ONE launch; x is
    // rounded in-kernel inside phase 1, h at the phase-1 epilogue.
    const int n4 = NUM_E * HH * DD / 4;
    round_w3x<<<2048, 256>>>((const float4*)w1, (float4*)pw1,
                             (const float4*)w3, (float4*)pw3,
                             (const float4*)w2, (float4*)pw2, n4);

    moe_mm<1, S1><<<dim3(HH / BN, TT / BM), NTHREADS, smem1>>>(x, cnt, nullptr);
    moe_mm<2, S2><<<dim3(DD / BN, TT / BM), NTHREADS, smem2>>>(nullptr, cnt, out);
}